// round 3
// baseline (speedup 1.0000x reference)
#include <cuda_runtime.h>
#include <cuda_bf16.h>
#include <math.h>

#define BATCH 65536
#define XDIM  362
#define NACT  3

// ---------------- scratch (device globals: allocation-free) ----------------
__device__ float g_att[BATCH * 6];
__device__ int   g_idx[BATCH * 6];
__device__ int   g_cnt[NACT];
__device__ int   g_ord[NACT * BATCH];
__device__ float g_h1[(size_t)BATCH * 100];
__device__ float g_h2[(size_t)BATCH * 400];
__device__ float g_h3[(size_t)BATCH * 100];

// ---------------- K0: reset action counters ----------------
__global__ void k_reset() {
    if (threadIdx.x < NACT) g_cnt[threadIdx.x] = 0;
}

// ---------------- K1: argmax + attention gather + copy x -> out ----------------
// warp per row. 8 warps / block.
__global__ __launch_bounds__(256) void k_att(const float* __restrict__ x,
                                             float* __restrict__ out) {
    int w    = threadIdx.x >> 5;
    int lane = threadIdx.x & 31;
    int s    = blockIdx.x * 8 + w;

    const float* row = x + (size_t)s * XDIM;
    float*      orow = out + (size_t)s * XDIM;

    float vmax = -INFINITY;
    int   imax = 0;
    for (int i = lane; i < XDIM; i += 32) {
        float v = row[i];
        orow[i] = v;
        if (v > vmax) { vmax = v; imax = i; }   // ascending i => first max kept
    }
    // warp reduce: larger value wins; tie -> smaller index
    for (int o = 16; o > 0; o >>= 1) {
        float ov = __shfl_down_sync(0xffffffffu, vmax, o);
        int   oi = __shfl_down_sync(0xffffffffu, imax, o);
        if (ov > vmax || (ov == vmax && oi < imax)) { vmax = ov; imax = oi; }
    }
    int ptr = __shfl_sync(0xffffffffu, imax, 0);

    if (lane < 6) {
        int idx;
        switch (lane) {
            case 0:  idx = 0; break;
            case 1:  idx = ptr; break;
            case 2:  idx = min(max(ptr - 19, 1), XDIM - 1); break;
            case 3:  idx = min(max(ptr + 19, 1), XDIM - 1); break;
            case 4:  idx = min(max(ptr - 1, 1), XDIM - 1); break;
            default: idx = min(max(ptr + 1, 1), XDIM - 1); break;
        }
        g_idx[s * 6 + lane] = idx;
        g_att[s * 6 + lane] = row[idx];
    }
}

// ---------------- K2: stream compaction by action (block-aggregated atomics) ----
__global__ __launch_bounds__(256) void k_group(const int* __restrict__ act) {
    int tid = threadIdx.x;
    int s   = blockIdx.x * 256 + tid;
    int a   = act[s];
    int w   = tid >> 5, lane = tid & 31;

    __shared__ int wcnt[8][NACT];
    __shared__ int woff[8][NACT];
    __shared__ int bbase[NACT];

    unsigned m0 = __ballot_sync(0xffffffffu, a == 0);
    unsigned m1 = __ballot_sync(0xffffffffu, a == 1);
    unsigned m2 = __ballot_sync(0xffffffffu, a == 2);
    if (lane == 0) {
        wcnt[w][0] = __popc(m0);
        wcnt[w][1] = __popc(m1);
        wcnt[w][2] = __popc(m2);
    }
    __syncthreads();
    if (tid < NACT) {
        int off = 0;
        for (int i = 0; i < 8; i++) { woff[i][tid] = off; off += wcnt[i][tid]; }
        bbase[tid] = atomicAdd(&g_cnt[tid], off);
    }
    __syncthreads();
    unsigned mym = (a == 0) ? m0 : ((a == 1) ? m1 : m2);
    int rank = __popc(mym & ((1u << lane) - 1u));
    int pos  = bbase[a] + woff[w][a] + rank;
    g_ord[a * BATCH + pos] = s;
}

// ---------------- K3: layer1 (6 -> 100), all 3 actions' weights in smem --------
__global__ __launch_bounds__(128) void k_l1(const float* __restrict__ W1,
                                            const float* __restrict__ b1,
                                            const int*   __restrict__ act) {
    __shared__ float W1s[NACT * 600];
    __shared__ float b1s[NACT * 100];
    for (int i = threadIdx.x; i < NACT * 600; i += 128) W1s[i] = W1[i];
    for (int i = threadIdx.x; i < NACT * 100; i += 128) b1s[i] = b1[i];
    __syncthreads();

    int row = blockIdx.x * 128 + threadIdx.x;
    int a   = act[row];
    float at[6];
#pragma unroll
    for (int k = 0; k < 6; k++) at[k] = g_att[row * 6 + k];

    const float* Wa = W1s + a * 600;
    const float* ba = b1s + a * 100;
    float* h = g_h1 + (size_t)row * 100;
    for (int j = 0; j < 100; j++) {
        float acc = ba[j];
#pragma unroll
        for (int k = 0; k < 6; k++) acc += at[k] * Wa[k * 100 + j];
        h[j] = fmaxf(acc, 0.f);
    }
}

// ---------------- K4: layer2 (100 -> 400) GEMM, W2[a] staged in smem -----------
// 64-row tile, 256 threads, each thread 4 rows x 25 cols.
extern __shared__ float smem2[];
__global__ __launch_bounds__(256, 1) void k_l2(const float* __restrict__ W2,
                                               const float* __restrict__ b2) {
    int a    = blockIdx.y;
    int cnt  = g_cnt[a];
    int base = blockIdx.x * 64;
    if (base >= cnt) return;

    float* W2s = smem2;             // 100*400 = 40000
    float* b2s = smem2 + 40000;     // 400
    float* h1s = smem2 + 40400;     // 64*100 = 6400
    int*   rid = (int*)(smem2 + 46800); // 64

    const float4* src = (const float4*)(W2 + (size_t)a * 40000);
    float4* dst = (float4*)W2s;
    for (int i = threadIdx.x; i < 10000; i += 256) dst[i] = src[i];
    for (int i = threadIdx.x; i < 400; i += 256) b2s[i] = b2[a * 400 + i];

    int nr = min(64, cnt - base);
    for (int i = threadIdx.x; i < 64; i += 256)
        rid[i] = (i < nr) ? g_ord[a * BATCH + base + i] : -1;
    __syncthreads();
    for (int i = threadIdx.x; i < 6400; i += 256) {
        int r = i / 100, k = i - r * 100;
        int id = rid[r];
        h1s[i] = (id >= 0) ? g_h1[(size_t)id * 100 + k] : 0.f;
    }
    __syncthreads();

    int tx = threadIdx.x & 15;
    int ty = threadIdx.x >> 4;       // 0..15, each owns 4 rows
    float acc[4][25];
#pragma unroll
    for (int rr = 0; rr < 4; rr++)
#pragma unroll
        for (int cc = 0; cc < 25; cc++) acc[rr][cc] = b2s[tx + 16 * cc];

    const float* hp = h1s + (ty * 4) * 100;
#pragma unroll 2
    for (int k = 0; k < 100; k++) {
        float h0 = hp[k], h1v = hp[100 + k], h2v = hp[200 + k], h3v = hp[300 + k];
        const float* wk = W2s + k * 400 + tx;
#pragma unroll
        for (int cc = 0; cc < 25; cc++) {
            float w = wk[cc * 16];
            acc[0][cc] += h0 * w;
            acc[1][cc] += h1v * w;
            acc[2][cc] += h2v * w;
            acc[3][cc] += h3v * w;
        }
    }
#pragma unroll
    for (int rr = 0; rr < 4; rr++) {
        int id = rid[ty * 4 + rr];
        if (id >= 0) {
            float* o = g_h2 + (size_t)id * 400 + tx;
#pragma unroll
            for (int cc = 0; cc < 25; cc++) o[cc * 16] = fmaxf(acc[rr][cc], 0.f);
        }
    }
}

// ---------------- K5: layer3 (400 -> 100) GEMM, W3[a] staged in smem -----------
// 32-row tile, 256 threads (2 warps/SMSP for latency hiding),
// each thread 2 rows x 7 cols (cols padded to 112).
extern __shared__ float smem3[];
__global__ __launch_bounds__(256, 1) void k_l3(const float* __restrict__ W3,
                                               const float* __restrict__ b3) {
    int a    = blockIdx.y;
    int cnt  = g_cnt[a];
    int base = blockIdx.x * 32;
    if (base >= cnt) return;

    float* W3s = smem3;              // 400*100 = 40000
    float* b3s = smem3 + 40000;      // 100
    float* h2s = smem3 + 40100;      // 32*404 = 12928 (padded stride, no bank conflict)
    int*   rid = (int*)(smem3 + 53028); // 32

    const float4* src = (const float4*)(W3 + (size_t)a * 40000);
    float4* dst = (float4*)W3s;
    for (int i = threadIdx.x; i < 10000; i += 256) dst[i] = src[i];
    for (int i = threadIdx.x; i < 100; i += 256) b3s[i] = b3[a * 100 + i];

    int nr = min(32, cnt - base);
    for (int i = threadIdx.x; i < 32; i += 256)
        rid[i] = (i < nr) ? g_ord[a * BATCH + base + i] : -1;
    __syncthreads();
    for (int i = threadIdx.x; i < 32 * 400; i += 256) {
        int r = i / 400, k = i - r * 400;
        int id = rid[r];
        h2s[r * 404 + k] = (id >= 0) ? g_h2[(size_t)id * 400 + k] : 0.f;
    }
    __syncthreads();

    int tx = threadIdx.x & 15;
    int ty = threadIdx.x >> 4;        // 0..15, each owns 2 rows
    bool ok6 = (tx + 96) < 100;       // col validity for cc==6
    float acc[2][7];
#pragma unroll
    for (int rr = 0; rr < 2; rr++)
#pragma unroll
        for (int cc = 0; cc < 7; cc++) {
            int c = tx + 16 * cc;
            acc[rr][cc] = (c < 100) ? b3s[c] : 0.f;
        }

    const float* hp = h2s + (ty * 2) * 404;
#pragma unroll 4
    for (int k = 0; k < 400; k++) {
        float h0 = hp[k], h1v = hp[404 + k];
        const float* wk = W3s + k * 100 + tx;
#pragma unroll
        for (int cc = 0; cc < 6; cc++) {
            float w = wk[cc * 16];
            acc[0][cc] += h0 * w;
            acc[1][cc] += h1v * w;
        }
        float w6 = ok6 ? wk[96] : 0.f;
        acc[0][6] += h0 * w6;
        acc[1][6] += h1v * w6;
    }
#pragma unroll
    for (int rr = 0; rr < 2; rr++) {
        int id = rid[ty * 2 + rr];
        if (id >= 0) {
            float* o = g_h3 + (size_t)id * 100;
#pragma unroll
            for (int cc = 0; cc < 7; cc++) {
                int c = tx + 16 * cc;
                if (c < 100) o[c] = fmaxf(acc[rr][cc], 0.f);
            }
        }
    }
}

// ---------------- K6: layer4 (100 -> 6) + scatter into out ---------------------
__global__ __launch_bounds__(256) void k_l4(const float* __restrict__ W4,
                                            const float* __restrict__ b4,
                                            const int*   __restrict__ act,
                                            float* __restrict__ out) {
    __shared__ float W4s[NACT * 600];
    __shared__ float b4s[NACT * 6];
    for (int i = threadIdx.x; i < NACT * 600; i += 256) W4s[i] = W4[i];
    if (threadIdx.x < NACT * 6) b4s[threadIdx.x] = b4[threadIdx.x];
    __syncthreads();

    int row = blockIdx.x * 256 + threadIdx.x;
    int a   = act[row];
    float pred[6];
#pragma unroll
    for (int j = 0; j < 6; j++) pred[j] = b4s[a * 6 + j];

    const float* h  = g_h3 + (size_t)row * 100;
    const float* Wa = W4s + a * 600;
    for (int k = 0; k < 100; k++) {
        float hv = h[k];
#pragma unroll
        for (int j = 0; j < 6; j++) pred[j] += hv * Wa[k * 6 + j];
    }
    // ascending j, same thread => program order => last index wins (matches ref)
    float* orow = out + (size_t)row * XDIM;
#pragma unroll
    for (int j = 0; j < 6; j++) {
        int id = g_idx[row * 6 + j];
        orow[id] = g_att[row * 6 + j] + pred[j];
    }
}

// ---------------- launch ----------------
extern "C" void kernel_launch(void* const* d_in, const int* in_sizes, int n_in,
                              void* d_out, int out_size) {
    const float* x  = (const float*)d_in[0];
    const float* W1 = (const float*)d_in[1];
    const float* b1 = (const float*)d_in[2];
    const float* W2 = (const float*)d_in[3];
    const float* b2 = (const float*)d_in[4];
    const float* W3 = (const float*)d_in[5];
    const float* b3 = (const float*)d_in[6];
    const float* W4 = (const float*)d_in[7];
    const float* b4 = (const float*)d_in[8];
    const int*   ba = (const int*)d_in[9];
    float* out = (float*)d_out;

    const int smem_l2 = 46864 * 4;   // 187456 B
    const int smem_l3 = 53060 * 4;   // 212240 B
    cudaFuncSetAttribute(k_l2, cudaFuncAttributeMaxDynamicSharedMemorySize, smem_l2);
    cudaFuncSetAttribute(k_l3, cudaFuncAttributeMaxDynamicSharedMemorySize, smem_l3);

    k_reset<<<1, 32>>>();
    k_att<<<BATCH / 8, 256>>>(x, out);
    k_group<<<BATCH / 256, 256>>>(ba);
    k_l1<<<BATCH / 128, 128>>>(W1, b1, ba);
    k_l2<<<dim3(BATCH / 64, NACT), 256, smem_l2>>>(W2, b2);
    k_l3<<<dim3(BATCH / 32, NACT), 256, smem_l3>>>(W3, b3);
    k_l4<<<BATCH / 256, 256>>>(W4, b4, ba, out);
}

// round 16
// speedup vs baseline: 1.2577x; 1.2577x over previous
#include <cuda_runtime.h>
#include <cuda_bf16.h>
#include <math.h>

#define BATCH 65536
#define XDIM  362
#define NACT  3

// ---------------- scratch (device globals: allocation-free) ----------------
__device__ float g_att[BATCH * 6];
__device__ int   g_idx[BATCH * 6];
__device__ int   g_cnt[NACT];
__device__ int   g_ord[NACT * BATCH];
__device__ float g_h1[(size_t)BATCH * 100];
__device__ float g_h2[(size_t)BATCH * 400];
__device__ float g_h3[(size_t)BATCH * 100];

// ---------------- K0: reset action counters ----------------
__global__ void k_reset() {
    if (threadIdx.x < NACT) g_cnt[threadIdx.x] = 0;
}

// ---------------- K1: argmax + attention gather + copy x -> out ----------------
__global__ __launch_bounds__(256) void k_att(const float* __restrict__ x,
                                             float* __restrict__ out) {
    int w    = threadIdx.x >> 5;
    int lane = threadIdx.x & 31;
    int s    = blockIdx.x * 8 + w;

    const float* row = x + (size_t)s * XDIM;
    float*      orow = out + (size_t)s * XDIM;

    float vmax = -INFINITY;
    int   imax = 0;
    for (int i = lane; i < XDIM; i += 32) {
        float v = row[i];
        orow[i] = v;
        if (v > vmax) { vmax = v; imax = i; }
    }
    for (int o = 16; o > 0; o >>= 1) {
        float ov = __shfl_down_sync(0xffffffffu, vmax, o);
        int   oi = __shfl_down_sync(0xffffffffu, imax, o);
        if (ov > vmax || (ov == vmax && oi < imax)) { vmax = ov; imax = oi; }
    }
    int ptr = __shfl_sync(0xffffffffu, imax, 0);

    if (lane < 6) {
        int idx;
        switch (lane) {
            case 0:  idx = 0; break;
            case 1:  idx = ptr; break;
            case 2:  idx = min(max(ptr - 19, 1), XDIM - 1); break;
            case 3:  idx = min(max(ptr + 19, 1), XDIM - 1); break;
            case 4:  idx = min(max(ptr - 1, 1), XDIM - 1); break;
            default: idx = min(max(ptr + 1, 1), XDIM - 1); break;
        }
        g_idx[s * 6 + lane] = idx;
        g_att[s * 6 + lane] = row[idx];
    }
}

// ---------------- K2: stream compaction by action ----------------
__global__ __launch_bounds__(256) void k_group(const int* __restrict__ act) {
    int tid = threadIdx.x;
    int s   = blockIdx.x * 256 + tid;
    int a   = act[s];
    int w   = tid >> 5, lane = tid & 31;

    __shared__ int wcnt[8][NACT];
    __shared__ int woff[8][NACT];
    __shared__ int bbase[NACT];

    unsigned m0 = __ballot_sync(0xffffffffu, a == 0);
    unsigned m1 = __ballot_sync(0xffffffffu, a == 1);
    unsigned m2 = __ballot_sync(0xffffffffu, a == 2);
    if (lane == 0) {
        wcnt[w][0] = __popc(m0);
        wcnt[w][1] = __popc(m1);
        wcnt[w][2] = __popc(m2);
    }
    __syncthreads();
    if (tid < NACT) {
        int off = 0;
        for (int i = 0; i < 8; i++) { woff[i][tid] = off; off += wcnt[i][tid]; }
        bbase[tid] = atomicAdd(&g_cnt[tid], off);
    }
    __syncthreads();
    unsigned mym = (a == 0) ? m0 : ((a == 1) ? m1 : m2);
    int rank = __popc(mym & ((1u << lane) - 1u));
    int pos  = bbase[a] + woff[w][a] + rank;
    g_ord[a * BATCH + pos] = s;
}

// ---------------- K3: layer1 (6 -> 100), warp per row, coalesced writes --------
__global__ __launch_bounds__(256) void k_l1(const float* __restrict__ W1,
                                            const float* __restrict__ b1,
                                            const int*   __restrict__ act) {
    __shared__ float W1s[NACT * 600];
    __shared__ float b1s[NACT * 100];
    for (int i = threadIdx.x; i < NACT * 600; i += 256) W1s[i] = W1[i];
    for (int i = threadIdx.x; i < NACT * 100; i += 256) b1s[i] = b1[i];
    __syncthreads();

    int w    = threadIdx.x >> 5;
    int lane = threadIdx.x & 31;
    int s    = blockIdx.x * 8 + w;

    int a = act[s];                             // broadcast load
    float av = (lane < 6) ? g_att[s * 6 + lane] : 0.f;
    float at0 = __shfl_sync(0xffffffffu, av, 0);
    float at1 = __shfl_sync(0xffffffffu, av, 1);
    float at2 = __shfl_sync(0xffffffffu, av, 2);
    float at3 = __shfl_sync(0xffffffffu, av, 3);
    float at4 = __shfl_sync(0xffffffffu, av, 4);
    float at5 = __shfl_sync(0xffffffffu, av, 5);

    const float* Wa = W1s + a * 600;
    const float* ba = b1s + a * 100;
    float* h = g_h1 + (size_t)s * 100;

#pragma unroll
    for (int cc = 0; cc < 4; cc++) {
        int c = lane + cc * 32;
        if (c < 100) {
            float acc = ba[c];
            acc += at0 * Wa[c];
            acc += at1 * Wa[100 + c];
            acc += at2 * Wa[200 + c];
            acc += at3 * Wa[300 + c];
            acc += at4 * Wa[400 + c];
            acc += at5 * Wa[500 + c];
            h[c] = fmaxf(acc, 0.f);             // coalesced
        }
    }
}

// ---------------- K4: layer2 (100 -> 400), col-split for 2 CTA/SM --------------
// Block = 64 rows x 200 cols (blockIdx.y = col half). 256 threads,
// thread tile = 2 rows x 25 cols. smem ~106.6 KB -> 2 CTAs/SM (16 warps).
extern __shared__ float smem2[];
__global__ __launch_bounds__(256, 2) void k_l2(const float* __restrict__ W2,
                                               const float* __restrict__ b2) {
    int a    = blockIdx.z;
    int half = blockIdx.y;
    int cnt  = g_cnt[a];
    int base = blockIdx.x * 64;
    if (base >= cnt) return;

    float* W2h = smem2;                 // 100*200 = 20000
    float* b2h = smem2 + 20000;         // 200
    float* h1s = smem2 + 20200;         // 64*100 = 6400
    int*   rid = (int*)(smem2 + 26600); // 64

    // stage W2 half: cols [half*200, half*200+200)
    {
        const float* Wg = W2 + (size_t)a * 40000 + half * 200;
        for (int i = threadIdx.x; i < 5000; i += 256) {      // 100 k * 50 float4
            int k = i / 50, q = i - k * 50;
            *(float4*)(W2h + k * 200 + q * 4) = *(const float4*)(Wg + k * 400 + q * 4);
        }
        for (int i = threadIdx.x; i < 200; i += 256)
            b2h[i] = b2[a * 400 + half * 200 + i];
    }
    int nr = min(64, cnt - base);
    for (int i = threadIdx.x; i < 64; i += 256)
        rid[i] = (i < nr) ? g_ord[a * BATCH + base + i] : -1;
    __syncthreads();
    for (int i = threadIdx.x; i < 6400; i += 256) {
        int r = i / 100, k = i - r * 100;
        int id = rid[r];
        h1s[i] = (id >= 0) ? g_h1[(size_t)id * 100 + k] : 0.f;
    }
    __syncthreads();

    int tx = threadIdx.x & 7;          // 8 col-threads
    int ty = threadIdx.x >> 3;         // 32 row-threads, 2 rows each
    float acc[2][25];
#pragma unroll
    for (int cc = 0; cc < 25; cc++) {
        float bb = b2h[tx + 8 * cc];
        acc[0][cc] = bb;
        acc[1][cc] = bb;
    }

    const float* hp = h1s + (ty * 2) * 100;
#pragma unroll 2
    for (int k = 0; k < 100; k++) {
        float h0 = hp[k], h1v = hp[100 + k];
        const float* wk = W2h + k * 200 + tx;
#pragma unroll
        for (int cc = 0; cc < 25; cc++) {
            float w = wk[cc * 8];
            acc[0][cc] += h0 * w;
            acc[1][cc] += h1v * w;
        }
    }
#pragma unroll
    for (int rr = 0; rr < 2; rr++) {
        int id = rid[ty * 2 + rr];
        if (id >= 0) {
            float* o = g_h2 + (size_t)id * 400 + half * 200 + tx;
#pragma unroll
            for (int cc = 0; cc < 25; cc++) o[cc * 8] = fmaxf(acc[rr][cc], 0.f);
        }
    }
}

// ---------------- K5: layer3 (400 -> 100), k-streamed weights ------------------
// Block = 64 rows x 100 cols, K=400 streamed in 2 stages of 200 through an
// 80 KB smem buffer. 512 threads (16 warps/SM), thread tile = 2 rows x 7 cols.
extern __shared__ float smem3[];
__global__ __launch_bounds__(512, 1) void k_l3(const float* __restrict__ W3,
                                               const float* __restrict__ b3) {
    int a    = blockIdx.y;
    int cnt  = g_cnt[a];
    int base = blockIdx.x * 64;
    if (base >= cnt) return;

    float* Wbuf = smem3;                 // 200*100 = 20000
    float* b3s  = smem3 + 20000;         // 100
    float* h2s  = smem3 + 20100;         // 64*404 = 25856 (padded stride)
    int*   rid  = (int*)(smem3 + 45956); // 64

    const float* Wg = W3 + (size_t)a * 40000;

    // stage 0 weights + bias + rid + h2 tile
    for (int i = threadIdx.x; i < 5000; i += 512)            // 200 k * 25 float4
        *(float4*)(Wbuf + i * 4) = *(const float4*)(Wg + i * 4);
    for (int i = threadIdx.x; i < 100; i += 512) b3s[i] = b3[a * 100 + i];
    int nr = min(64, cnt - base);
    for (int i = threadIdx.x; i < 64; i += 512)
        rid[i] = (i < nr) ? g_ord[a * BATCH + base + i] : -1;
    __syncthreads();
    for (int i = threadIdx.x; i < 64 * 400; i += 512) {
        int r = i / 400, k = i - r * 400;
        int id = rid[r];
        h2s[r * 404 + k] = (id >= 0) ? g_h2[(size_t)id * 400 + k] : 0.f;
    }
    __syncthreads();

    int tx = threadIdx.x & 15;         // 16 col-threads
    int ty = threadIdx.x >> 4;         // 32 row-threads, 2 rows each
    bool ok6 = (tx + 96) < 100;
    float acc[2][7];
#pragma unroll
    for (int cc = 0; cc < 7; cc++) {
        int c = tx + 16 * cc;
        float bb = (c < 100) ? b3s[c] : 0.f;
        acc[0][cc] = bb;
        acc[1][cc] = bb;
    }

    const float* hp = h2s + (ty * 2) * 404;

    // stage 0: k in [0,200)
#pragma unroll 2
    for (int k = 0; k < 200; k++) {
        float h0 = hp[k], h1v = hp[404 + k];
        const float* wk = Wbuf + k * 100 + tx;
#pragma unroll
        for (int cc = 0; cc < 6; cc++) {
            float w = wk[cc * 16];
            acc[0][cc] += h0 * w;
            acc[1][cc] += h1v * w;
        }
        float w6 = ok6 ? wk[96] : 0.f;
        acc[0][6] += h0 * w6;
        acc[1][6] += h1v * w6;
    }
    __syncthreads();
    // stage 1 weights: k in [200,400)
    for (int i = threadIdx.x; i < 5000; i += 512)
        *(float4*)(Wbuf + i * 4) = *(const float4*)(Wg + 20000 + i * 4);
    __syncthreads();
#pragma unroll 2
    for (int k = 0; k < 200; k++) {
        float h0 = hp[200 + k], h1v = hp[404 + 200 + k];
        const float* wk = Wbuf + k * 100 + tx;
#pragma unroll
        for (int cc = 0; cc < 6; cc++) {
            float w = wk[cc * 16];
            acc[0][cc] += h0 * w;
            acc[1][cc] += h1v * w;
        }
        float w6 = ok6 ? wk[96] : 0.f;
        acc[0][6] += h0 * w6;
        acc[1][6] += h1v * w6;
    }

#pragma unroll
    for (int rr = 0; rr < 2; rr++) {
        int id = rid[ty * 2 + rr];
        if (id >= 0) {
            float* o = g_h3 + (size_t)id * 100;
#pragma unroll
            for (int cc = 0; cc < 7; cc++) {
                int c = tx + 16 * cc;
                if (c < 100) o[c] = fmaxf(acc[rr][cc], 0.f);
            }
        }
    }
}

// ---------------- K6: layer4 (100 -> 6) + scatter, warp per row ----------------
__global__ __launch_bounds__(256) void k_l4(const float* __restrict__ W4,
                                            const float* __restrict__ b4,
                                            const int*   __restrict__ act,
                                            float* __restrict__ out) {
    __shared__ float W4s[NACT * 600];
    __shared__ float b4s[NACT * 6];
    for (int i = threadIdx.x; i < NACT * 600; i += 256) W4s[i] = W4[i];
    if (threadIdx.x < NACT * 6) b4s[threadIdx.x] = b4[threadIdx.x];
    __syncthreads();

    int w    = threadIdx.x >> 5;
    int lane = threadIdx.x & 31;
    int s    = blockIdx.x * 8 + w;
    int a    = act[s];                         // broadcast

    const float* h = g_h3 + (size_t)s * 100;   // coalesced reads
    float hv0 = h[lane];
    float hv1 = h[lane + 32];
    float hv2 = h[lane + 64];
    float hv3 = (lane < 4) ? h[lane + 96] : 0.f;

    const float* Wa = W4s + a * 600;
    float p[6];
#pragma unroll
    for (int j = 0; j < 6; j++) {
        float acc;
        acc  = hv0 * Wa[lane * 6 + j];
        acc += hv1 * Wa[(lane + 32) * 6 + j];
        acc += hv2 * Wa[(lane + 64) * 6 + j];
        if (lane < 4) acc += hv3 * Wa[(lane + 96) * 6 + j];
        // butterfly all-reduce
#pragma unroll
        for (int o = 16; o > 0; o >>= 1)
            acc += __shfl_xor_sync(0xffffffffu, acc, o);
        p[j] = acc;
    }

    if (lane == 0) {
        float* orow = out + (size_t)s * XDIM;
#pragma unroll
        for (int j = 0; j < 6; j++) {          // ascending j: last index wins
            int id = g_idx[s * 6 + j];
            orow[id] = g_att[s * 6 + j] + p[j] + b4s[a * 6 + j];
        }
    }
}

// ---------------- launch ----------------
extern "C" void kernel_launch(void* const* d_in, const int* in_sizes, int n_in,
                              void* d_out, int out_size) {
    const float* x  = (const float*)d_in[0];
    const float* W1 = (const float*)d_in[1];
    const float* b1 = (const float*)d_in[2];
    const float* W2 = (const float*)d_in[3];
    const float* b2 = (const float*)d_in[4];
    const float* W3 = (const float*)d_in[5];
    const float* b3 = (const float*)d_in[6];
    const float* W4 = (const float*)d_in[7];
    const float* b4 = (const float*)d_in[8];
    const int*   ba = (const int*)d_in[9];
    float* out = (float*)d_out;

    const int smem_l2 = 26664 * 4;   // 106656 B  -> 2 CTAs/SM
    const int smem_l3 = 46020 * 4;   // 184080 B  -> 1 CTA/SM, 16 warps
    cudaFuncSetAttribute(k_l2, cudaFuncAttributeMaxDynamicSharedMemorySize, smem_l2);
    cudaFuncSetAttribute(k_l3, cudaFuncAttributeMaxDynamicSharedMemorySize, smem_l3);

    k_reset<<<1, 32>>>();
    k_att<<<BATCH / 8, 256>>>(x, out);
    k_group<<<BATCH / 256, 256>>>(ba);
    k_l1<<<BATCH / 8, 256>>>(W1, b1, ba);
    k_l2<<<dim3(BATCH / 64, 2, NACT), 256, smem_l2>>>(W2, b2);
    k_l3<<<dim3(BATCH / 64, NACT), 512, smem_l3>>>(W3, b3);
    k_l4<<<BATCH / 8, 256>>>(W4, b4, ba, out);
}

// round 17
// speedup vs baseline: 1.6772x; 1.3335x over previous
#include <cuda_runtime.h>
#include <cuda_bf16.h>
#include <math.h>

#define BATCH 65536
#define XDIM  362
#define NACT  3

// ---------------- scratch (device globals: allocation-free) ----------------
__device__ float g_att[BATCH * 6];
__device__ int   g_idx[BATCH * 6];
__device__ int   g_cnt[NACT];
__device__ int   g_ord[NACT * BATCH];
__device__ float g_h1[(size_t)BATCH * 100];
__device__ float g_h2[(size_t)BATCH * 400];
__device__ float g_h3[(size_t)BATCH * 100];

// ---------------- K0: reset action counters ----------------
__global__ void k_reset() {
    if (threadIdx.x < NACT) g_cnt[threadIdx.x] = 0;
}

// ---------------- K1: argmax + attention gather + copy x -> out ----------------
__global__ __launch_bounds__(256) void k_att(const float* __restrict__ x,
                                             float* __restrict__ out) {
    int w    = threadIdx.x >> 5;
    int lane = threadIdx.x & 31;
    int s    = blockIdx.x * 8 + w;

    const float* row = x + (size_t)s * XDIM;
    float*      orow = out + (size_t)s * XDIM;

    float vmax = -INFINITY;
    int   imax = 0;
    for (int i = lane; i < XDIM; i += 32) {
        float v = row[i];
        orow[i] = v;
        if (v > vmax) { vmax = v; imax = i; }
    }
    for (int o = 16; o > 0; o >>= 1) {
        float ov = __shfl_down_sync(0xffffffffu, vmax, o);
        int   oi = __shfl_down_sync(0xffffffffu, imax, o);
        if (ov > vmax || (ov == vmax && oi < imax)) { vmax = ov; imax = oi; }
    }
    int ptr = __shfl_sync(0xffffffffu, imax, 0);

    if (lane < 6) {
        int idx;
        switch (lane) {
            case 0:  idx = 0; break;
            case 1:  idx = ptr; break;
            case 2:  idx = min(max(ptr - 19, 1), XDIM - 1); break;
            case 3:  idx = min(max(ptr + 19, 1), XDIM - 1); break;
            case 4:  idx = min(max(ptr - 1, 1), XDIM - 1); break;
            default: idx = min(max(ptr + 1, 1), XDIM - 1); break;
        }
        g_idx[s * 6 + lane] = idx;
        g_att[s * 6 + lane] = row[idx];
    }
}

// ---------------- K2: stream compaction by action ----------------
__global__ __launch_bounds__(256) void k_group(const int* __restrict__ act) {
    int tid = threadIdx.x;
    int s   = blockIdx.x * 256 + tid;
    int a   = act[s];
    int w   = tid >> 5, lane = tid & 31;

    __shared__ int wcnt[8][NACT];
    __shared__ int woff[8][NACT];
    __shared__ int bbase[NACT];

    unsigned m0 = __ballot_sync(0xffffffffu, a == 0);
    unsigned m1 = __ballot_sync(0xffffffffu, a == 1);
    unsigned m2 = __ballot_sync(0xffffffffu, a == 2);
    if (lane == 0) {
        wcnt[w][0] = __popc(m0);
        wcnt[w][1] = __popc(m1);
        wcnt[w][2] = __popc(m2);
    }
    __syncthreads();
    if (tid < NACT) {
        int off = 0;
        for (int i = 0; i < 8; i++) { woff[i][tid] = off; off += wcnt[i][tid]; }
        bbase[tid] = atomicAdd(&g_cnt[tid], off);
    }
    __syncthreads();
    unsigned mym = (a == 0) ? m0 : ((a == 1) ? m1 : m2);
    int rank = __popc(mym & ((1u << lane) - 1u));
    int pos  = bbase[a] + woff[w][a] + rank;
    g_ord[a * BATCH + pos] = s;
}

// ---------------- K3: layer1 (6 -> 100), warp per row, coalesced writes --------
__global__ __launch_bounds__(256) void k_l1(const float* __restrict__ W1,
                                            const float* __restrict__ b1,
                                            const int*   __restrict__ act) {
    __shared__ float W1s[NACT * 600];
    __shared__ float b1s[NACT * 100];
    for (int i = threadIdx.x; i < NACT * 600; i += 256) W1s[i] = W1[i];
    for (int i = threadIdx.x; i < NACT * 100; i += 256) b1s[i] = b1[i];
    __syncthreads();

    int w    = threadIdx.x >> 5;
    int lane = threadIdx.x & 31;
    int s    = blockIdx.x * 8 + w;

    int a = act[s];                             // broadcast load
    float av = (lane < 6) ? g_att[s * 6 + lane] : 0.f;
    float at0 = __shfl_sync(0xffffffffu, av, 0);
    float at1 = __shfl_sync(0xffffffffu, av, 1);
    float at2 = __shfl_sync(0xffffffffu, av, 2);
    float at3 = __shfl_sync(0xffffffffu, av, 3);
    float at4 = __shfl_sync(0xffffffffu, av, 4);
    float at5 = __shfl_sync(0xffffffffu, av, 5);

    const float* Wa = W1s + a * 600;
    const float* ba = b1s + a * 100;
    float* h = g_h1 + (size_t)s * 100;

#pragma unroll
    for (int cc = 0; cc < 4; cc++) {
        int c = lane + cc * 32;
        if (c < 100) {
            float acc = ba[c];
            acc += at0 * Wa[c];
            acc += at1 * Wa[100 + c];
            acc += at2 * Wa[200 + c];
            acc += at3 * Wa[300 + c];
            acc += at4 * Wa[400 + c];
            acc += at5 * Wa[500 + c];
            h[c] = fmaxf(acc, 0.f);             // coalesced
        }
    }
}

// ---------------- K4: layer2 (100 -> 400), lane-across-cols tile ---------------
// Tile 64 rows x 400 cols. 512 threads = 16 warps x 4 rows; lane covers cols
// {lane, lane+32, ..., lane+384} (13 per lane, j=12 valid iff lane<16).
// Per warp per k-iter: 4 broadcast h-LDS + 13 coalesced weight-LDS vs 52 FFMA
// -> FFMA-bound (2*52=104 > 4*17=68). smem 193.9 KB, 16 warps/SM.
extern __shared__ float smem2[];
__global__ __launch_bounds__(512, 1) void k_l2(const float* __restrict__ W2,
                                               const float* __restrict__ b2) {
    int a    = blockIdx.y;
    int cnt  = g_cnt[a];
    int base = blockIdx.x * 64;
    if (base >= cnt) return;

    float* W2s = smem2;                  // 100 k * 416 (pad) = 41600
    float* h1s = smem2 + 41600;          // 64*100 = 6400
    float* b2s = smem2 + 48000;          // 400
    int*   rid = (int*)(smem2 + 48400);  // 64
    // total 48464 floats = 193856 B

    // stage W2 (100x400 row-major -> stride-416 smem), vectorized
    {
        const float4* src = (const float4*)(W2 + (size_t)a * 40000);
        for (int i = threadIdx.x; i < 10000; i += 512) {
            int k = i / 100, q = i - k * 100;
            *(float4*)(W2s + k * 416 + q * 4) = src[i];
        }
        for (int i = threadIdx.x; i < 400; i += 512)
            b2s[i] = b2[a * 400 + i];
    }
    int nr = min(64, cnt - base);
    for (int i = threadIdx.x; i < 64; i += 512)
        rid[i] = (i < nr) ? g_ord[a * BATCH + base + i] : -1;
    __syncthreads();
    for (int i = threadIdx.x; i < 1600; i += 512) {      // 64 rows * 25 float4
        int r = i / 25, q = i - r * 25;
        int id = rid[r];
        float4 v = (id >= 0) ? *(const float4*)(g_h1 + (size_t)id * 100 + q * 4)
                             : make_float4(0.f, 0.f, 0.f, 0.f);
        *(float4*)(h1s + r * 100 + q * 4) = v;
    }
    __syncthreads();

    int w    = threadIdx.x >> 5;        // warp 0..15 -> rows 4w..4w+3
    int lane = threadIdx.x & 31;
    bool ok12 = lane < 16;              // col lane+384 < 400

    float acc[4][13];
#pragma unroll
    for (int j = 0; j < 13; j++) {
        int c = lane + 32 * j;
        float bb = (c < 400) ? b2s[c] : 0.f;
#pragma unroll
        for (int r = 0; r < 4; r++) acc[r][j] = bb;
    }

    const float* hp = h1s + (w * 4) * 100;
#pragma unroll 2
    for (int k = 0; k < 100; k++) {
        float h0 = hp[k], h1v = hp[100 + k], h2v = hp[200 + k], h3v = hp[300 + k];
        const float* wk = W2s + k * 416 + lane;
#pragma unroll
        for (int j = 0; j < 13; j++) {
            float wv = (j < 12 || ok12) ? wk[j * 32] : 0.f;
            acc[0][j] += h0 * wv;
            acc[1][j] += h1v * wv;
            acc[2][j] += h2v * wv;
            acc[3][j] += h3v * wv;
        }
    }
#pragma unroll
    for (int r = 0; r < 4; r++) {
        int id = rid[w * 4 + r];
        if (id >= 0) {
            float* o = g_h2 + (size_t)id * 400 + lane;
#pragma unroll
            for (int j = 0; j < 12; j++) o[j * 32] = fmaxf(acc[r][j], 0.f);
            if (ok12) o[384] = fmaxf(acc[r][12], 0.f);
        }
    }
}

// ---------------- K5: layer3 (400 -> 100), lane-across-cols, k-streamed --------
// Tile 96 rows x 100 cols. 512 threads = 16 warps x 6 rows; lane covers cols
// {lane, lane+32, lane+64, lane+96} (j=3 valid iff lane<4). K=400 streamed in
// 4 stages of 100 through a 51.2 KB buffer. Per warp per k-iter: 6 broadcast
// h-LDS + 4 coalesced weight-LDS vs 24 FFMA -> FFMA-bound (48 > 40).
extern __shared__ float smem3[];
__global__ __launch_bounds__(512, 1) void k_l3(const float* __restrict__ W3,
                                               const float* __restrict__ b3) {
    int a    = blockIdx.y;
    int cnt  = g_cnt[a];
    int base = blockIdx.x * 96;
    if (base >= cnt) return;

    float* Wbuf = smem3;                  // 100 k * 128 (pad) = 12800
    float* h2s  = smem3 + 12800;          // 96*400 = 38400
    float* b3s  = smem3 + 51200;          // 128
    int*   rid  = (int*)(smem3 + 51328);  // 96
    // total 51424 floats = 205696 B

    const float* Wg = W3 + (size_t)a * 40000;

    // stage 0 weights (rows k=0..99 of 400x100) + bias + rid + h2 tile
    {
        const float4* src = (const float4*)Wg;
        for (int i = threadIdx.x; i < 2500; i += 512) {   // 100 k * 25 float4
            int k = i / 25, q = i - k * 25;
            *(float4*)(Wbuf + k * 128 + q * 4) = src[i];
        }
    }
    for (int i = threadIdx.x; i < 100; i += 512) b3s[i] = b3[a * 100 + i];
    int nr = min(96, cnt - base);
    for (int i = threadIdx.x; i < 96; i += 512)
        rid[i] = (i < nr) ? g_ord[a * BATCH + base + i] : -1;
    __syncthreads();
    for (int i = threadIdx.x; i < 9600; i += 512) {       // 96 rows * 100 float4
        int r = i / 100, q = i - r * 100;
        int id = rid[r];
        float4 v = (id >= 0) ? *(const float4*)(g_h2 + (size_t)id * 400 + q * 4)
                             : make_float4(0.f, 0.f, 0.f, 0.f);
        *(float4*)(h2s + r * 400 + q * 4) = v;
    }
    __syncthreads();

    int w    = threadIdx.x >> 5;        // warp 0..15 -> rows 6w..6w+5
    int lane = threadIdx.x & 31;
    bool ok3 = lane < 4;                // col lane+96 < 100

    float acc[6][4];
#pragma unroll
    for (int j = 0; j < 4; j++) {
        int c = lane + 32 * j;
        float bb = (c < 100) ? b3s[c] : 0.f;
#pragma unroll
        for (int r = 0; r < 6; r++) acc[r][j] = bb;
    }

    const float* hp = h2s + (w * 6) * 400;

#pragma unroll 1
    for (int stage = 0; stage < 4; stage++) {
        if (stage > 0) {
            __syncthreads();
            const float4* src = (const float4*)(Wg + stage * 10000);
            for (int i = threadIdx.x; i < 2500; i += 512) {
                int k = i / 25, q = i - k * 25;
                *(float4*)(Wbuf + k * 128 + q * 4) = src[i];
            }
            __syncthreads();
        }
        const float* hs = hp + stage * 100;
#pragma unroll 2
        for (int k = 0; k < 100; k++) {
            float h0 = hs[k],        h1v = hs[400 + k],  h2v = hs[800 + k];
            float h3 = hs[1200 + k], h4v = hs[1600 + k], h5v = hs[2000 + k];
            const float* wk = Wbuf + k * 128 + lane;
            float w0 = wk[0], w1 = wk[32], w2 = wk[64];
            float w3 = ok3 ? wk[96] : 0.f;
            acc[0][0] += h0 * w0;  acc[0][1] += h0 * w1;  acc[0][2] += h0 * w2;  acc[0][3] += h0 * w3;
            acc[1][0] += h1v * w0; acc[1][1] += h1v * w1; acc[1][2] += h1v * w2; acc[1][3] += h1v * w3;
            acc[2][0] += h2v * w0; acc[2][1] += h2v * w1; acc[2][2] += h2v * w2; acc[2][3] += h2v * w3;
            acc[3][0] += h3 * w0;  acc[3][1] += h3 * w1;  acc[3][2] += h3 * w2;  acc[3][3] += h3 * w3;
            acc[4][0] += h4v * w0; acc[4][1] += h4v * w1; acc[4][2] += h4v * w2; acc[4][3] += h4v * w3;
            acc[5][0] += h5v * w0; acc[5][1] += h5v * w1; acc[5][2] += h5v * w2; acc[5][3] += h5v * w3;
        }
    }

#pragma unroll
    for (int r = 0; r < 6; r++) {
        int id = rid[w * 6 + r];
        if (id >= 0) {
            float* o = g_h3 + (size_t)id * 100 + lane;
            o[0]  = fmaxf(acc[r][0], 0.f);
            o[32] = fmaxf(acc[r][1], 0.f);
            o[64] = fmaxf(acc[r][2], 0.f);
            if (ok3) o[96] = fmaxf(acc[r][3], 0.f);
        }
    }
}

// ---------------- K6: layer4 (100 -> 6) + scatter, warp per row ----------------
__global__ __launch_bounds__(256) void k_l4(const float* __restrict__ W4,
                                            const float* __restrict__ b4,
                                            const int*   __restrict__ act,
                                            float* __restrict__ out) {
    __shared__ float W4s[NACT * 600];
    __shared__ float b4s[NACT * 6];
    for (int i = threadIdx.x; i < NACT * 600; i += 256) W4s[i] = W4[i];
    if (threadIdx.x < NACT * 6) b4s[threadIdx.x] = b4[threadIdx.x];
    __syncthreads();

    int w    = threadIdx.x >> 5;
    int lane = threadIdx.x & 31;
    int s    = blockIdx.x * 8 + w;
    int a    = act[s];                         // broadcast

    const float* h = g_h3 + (size_t)s * 100;   // coalesced reads
    float hv0 = h[lane];
    float hv1 = h[lane + 32];
    float hv2 = h[lane + 64];
    float hv3 = (lane < 4) ? h[lane + 96] : 0.f;

    const float* Wa = W4s + a * 600;
    float p[6];
#pragma unroll
    for (int j = 0; j < 6; j++) {
        float acc;
        acc  = hv0 * Wa[lane * 6 + j];
        acc += hv1 * Wa[(lane + 32) * 6 + j];
        acc += hv2 * Wa[(lane + 64) * 6 + j];
        if (lane < 4) acc += hv3 * Wa[(lane + 96) * 6 + j];
        // butterfly all-reduce
#pragma unroll
        for (int o = 16; o > 0; o >>= 1)
            acc += __shfl_xor_sync(0xffffffffu, acc, o);
        p[j] = acc;
    }

    if (lane == 0) {
        float* orow = out + (size_t)s * XDIM;
#pragma unroll
        for (int j = 0; j < 6; j++) {          // ascending j: last index wins
            int id = g_idx[s * 6 + j];
            orow[id] = g_att[s * 6 + j] + p[j] + b4s[a * 6 + j];
        }
    }
}

// ---------------- launch ----------------
extern "C" void kernel_launch(void* const* d_in, const int* in_sizes, int n_in,
                              void* d_out, int out_size) {
    const float* x  = (const float*)d_in[0];
    const float* W1 = (const float*)d_in[1];
    const float* b1 = (const float*)d_in[2];
    const float* W2 = (const float*)d_in[3];
    const float* b2 = (const float*)d_in[4];
    const float* W3 = (const float*)d_in[5];
    const float* b3 = (const float*)d_in[6];
    const float* W4 = (const float*)d_in[7];
    const float* b4 = (const float*)d_in[8];
    const int*   ba = (const int*)d_in[9];
    float* out = (float*)d_out;

    const int smem_l2 = 48464 * 4;   // 193856 B
    const int smem_l3 = 51424 * 4;   // 205696 B
    cudaFuncSetAttribute(k_l2, cudaFuncAttributeMaxDynamicSharedMemorySize, smem_l2);
    cudaFuncSetAttribute(k_l3, cudaFuncAttributeMaxDynamicSharedMemorySize, smem_l3);

    k_reset<<<1, 32>>>();
    k_att<<<BATCH / 8, 256>>>(x, out);
    k_group<<<BATCH / 256, 256>>>(ba);
    k_l1<<<BATCH / 8, 256>>>(W1, b1, ba);
    k_l2<<<dim3(BATCH / 64, NACT), 512, smem_l2>>>(W2, b2);
    k_l3<<<dim3((BATCH + 95) / 96, NACT), 512, smem_l3>>>(W3, b3);
    k_l4<<<BATCH / 8, 256>>>(W4, b4, ba, out);
}